// round 9
// baseline (speedup 1.0000x reference)
#include <cuda_runtime.h>
#include <cstdint>

// Haar inverse DWT2 (db1), fp32.  Inputs A,H,V,D: [8,32,256,256]; out: [8,32,512,512].
// x[2i,2j]=(A+H+V+D)/2; x[2i,2j+1]=(A+H-V-D)/2; x[2i+1,2j]=(A-H+V-D)/2; x[2i+1,2j+1]=(A-H-V+D)/2
//
// R9 probe: isolate "per-thread work" from "load width" (R2 bundled both).
// Keep LDG.64 (proven request size), but each thread handles TWO float2 work
// items: t and t + N/2 (half-array split, both halves warp-coalesced).
// 8 front-batched LDG.64s per thread (MLP_p1=8), 4x STG.128, ~30 regs.

__global__ void __launch_bounds__(512) idwt2_haar_kernel(
    const float2* __restrict__ A,
    const float2* __restrict__ H,
    const float2* __restrict__ V,
    const float2* __restrict__ D,
    float4* __restrict__ out,
    unsigned half)              // = total float2 count / 2 = 4,194,304
{
    const unsigned t0 = blockIdx.x * 512u + threadIdx.x;
    const unsigned t1 = t0 + half;

    // front-batch all 8 loads (independent -> deep MLP)
    const float2 a0 = __ldg(&A[t0]);
    const float2 h0 = __ldg(&H[t0]);
    const float2 v0 = __ldg(&V[t0]);
    const float2 d0 = __ldg(&D[t0]);
    const float2 a1 = __ldg(&A[t1]);
    const float2 h1 = __ldg(&H[t1]);
    const float2 v1 = __ldg(&V[t1]);
    const float2 d1 = __ldg(&D[t1]);

    // work item 0
    {
        float lp0 = a0.x + h0.x, lm0 = a0.x - h0.x;
        float mp0 = v0.x + d0.x, mm0 = v0.x - d0.x;
        float lp1 = a0.y + h0.y, lm1 = a0.y - h0.y;
        float mp1 = v0.y + d0.y, mm1 = v0.y - d0.y;

        float4 even, odd;
        even.x = (lp0 + mp0) * 0.5f;
        even.y = (lp0 - mp0) * 0.5f;
        even.z = (lp1 + mp1) * 0.5f;
        even.w = (lp1 - mp1) * 0.5f;
        odd.x  = (lm0 + mm0) * 0.5f;
        odd.y  = (lm0 - mm0) * 0.5f;
        odd.z  = (lm1 + mm1) * 0.5f;
        odd.w  = (lm1 - mm1) * 0.5f;

        const unsigned o = ((t0 >> 7) << 8) + (t0 & 127u);
        out[o]        = even;
        out[o + 128u] = odd;
    }

    // work item 1
    {
        float lp0 = a1.x + h1.x, lm0 = a1.x - h1.x;
        float mp0 = v1.x + d1.x, mm0 = v1.x - d1.x;
        float lp1 = a1.y + h1.y, lm1 = a1.y - h1.y;
        float mp1 = v1.y + d1.y, mm1 = v1.y - d1.y;

        float4 even, odd;
        even.x = (lp0 + mp0) * 0.5f;
        even.y = (lp0 - mp0) * 0.5f;
        even.z = (lp1 + mp1) * 0.5f;
        even.w = (lp1 - mp1) * 0.5f;
        odd.x  = (lm0 + mm0) * 0.5f;
        odd.y  = (lm0 - mm0) * 0.5f;
        odd.z  = (lm1 + mm1) * 0.5f;
        odd.w  = (lm1 - mm1) * 0.5f;

        const unsigned o = ((t1 >> 7) << 8) + (t1 & 127u);
        out[o]        = even;
        out[o + 128u] = odd;
    }
}

extern "C" void kernel_launch(void* const* d_in, const int* in_sizes, int n_in,
                              void* d_out, int out_size)
{
    const float2* A = (const float2*)d_in[0];
    const float2* H = (const float2*)d_in[1];
    const float2* V = (const float2*)d_in[2];
    const float2* D = (const float2*)d_in[3];
    float4* out = (float4*)d_out;

    const unsigned n_f2   = (unsigned)(in_sizes[0] / 2);  // 8,388,608
    const unsigned half   = n_f2 / 2;                      // 4,194,304
    const unsigned blocks = (half + 511u) / 512u;          // 8192

    idwt2_haar_kernel<<<blocks, 512>>>(A, H, V, D, out, half);
}

// round 11
// speedup vs baseline: 1.0186x; 1.0186x over previous
#include <cuda_runtime.h>
#include <cstdint>

// Haar inverse DWT2 (db1), fp32.  Inputs A,H,V,D: [8,32,256,256]; out: [8,32,512,512].
// x[2i,2j]=(A+H+V+D)/2; x[2i,2j+1]=(A+H-V-D)/2; x[2i+1,2j]=(A-H+V-D)/2; x[2i+1,2j+1]=(A-H-V+D)/2
//
// FINAL (R4 champion, locked after 9-round search):
//   one thread per float2 of input -> 4x LDG.64 + 2x STG.128, 18 regs, block=512.
//   ~7.3 TB/s effective (~91% of 8 TB/s HBM spec) on the 50/50 R/W mix:
//   at the bus-turnaround-limited ceiling for this zero-reuse butterfly.
// Single-variable bracketing (all measured):
//   load width 128-bit   -> -6%   (L1tex wavefront doubling; R2)
//   per-thread work x2   -> tie   (issue was never the limiter; R9)
//   block 256 / 1024     -> -1/-2% (burst locality vs concurrency peak at 512; R1/R5)
//   .cs load/store hints -> neutral-to-negative (R3/R6)
//   noise band           -> +/-1.5 us (R7/R8 identity re-benches)

__global__ void __launch_bounds__(512) idwt2_haar_kernel(
    const float2* __restrict__ A,
    const float2* __restrict__ H,
    const float2* __restrict__ V,
    const float2* __restrict__ D,
    float4* __restrict__ out)
{
    // total threads = 8*32*256*256 / 2 = 8,388,608
    const unsigned t = blockIdx.x * 512u + threadIdx.x;

    const float2 a = __ldg(&A[t]);
    const float2 h = __ldg(&H[t]);
    const float2 v = __ldg(&V[t]);
    const float2 d = __ldg(&D[t]);

    float lp0 = a.x + h.x, lm0 = a.x - h.x;
    float mp0 = v.x + d.x, mm0 = v.x - d.x;
    float lp1 = a.y + h.y, lm1 = a.y - h.y;
    float mp1 = v.y + d.y, mm1 = v.y - d.y;

    float4 even, odd;
    even.x = (lp0 + mp0) * 0.5f;
    even.y = (lp0 - mp0) * 0.5f;
    even.z = (lp1 + mp1) * 0.5f;
    even.w = (lp1 - mp1) * 0.5f;
    odd.x  = (lm0 + mm0) * 0.5f;
    odd.y  = (lm0 - mm0) * 0.5f;
    odd.z  = (lm1 + mm1) * 0.5f;
    odd.w  = (lm1 - mm1) * 0.5f;

    // t = b*32768 + i*128 + j2 ; even-row out f4 index = ((t>>7)<<8) + (t&127)
    const unsigned o = ((t >> 7) << 8) + (t & 127u);
    out[o]        = even;
    out[o + 128u] = odd;   // odd row: +512 floats = +128 float4s
}

extern "C" void kernel_launch(void* const* d_in, const int* in_sizes, int n_in,
                              void* d_out, int out_size)
{
    const float2* A = (const float2*)d_in[0];
    const float2* H = (const float2*)d_in[1];
    const float2* V = (const float2*)d_in[2];
    const float2* D = (const float2*)d_in[3];
    float4* out = (float4*)d_out;

    const unsigned n_threads = (unsigned)(in_sizes[0] / 2);
    const unsigned blocks = (n_threads + 511u) / 512u;

    idwt2_haar_kernel<<<blocks, 512>>>(A, H, V, D, out);
}